// round 2
// baseline (speedup 1.0000x reference)
#include <cuda_runtime.h>
#include <math.h>
#include <stdint.h>

#define DIMK 128
#define RQ   131072
#define BB   1024
#define NN   10
#define NM   (BB*NN)      /* 10240 */
#define INVT 10.0f        /* 1/TEMP */

/* ------------------------------------------------------------------ */
/* scratch (static device allocations — no cudaMalloc allowed)         */
/* ------------------------------------------------------------------ */
__device__ float g_fn[2][BB*DIMK];          // normalized feats
__device__ float g_sim[268435456];          // 2 * 1024 * 131072 sims (1 GiB)
__device__ int   g_topk[2*NM];              // top-10 indices per row per side
__device__ float g_nnT[2][DIMK*NM];         // gathered neighbors, transposed [d][m]
__device__ float g_lse[2*BB];
__device__ float g_pos[2*BB];

/* ------------------------------------------------------------------ */
/* 1. row-normalize feats; also scatter f.T into output queue[:, :B]   */
/* ------------------------------------------------------------------ */
__global__ void k_normalize(const float* __restrict__ fX,
                            const float* __restrict__ fY,
                            float* __restrict__ out)
{
    int b = blockIdx.x, side = blockIdx.y, d = threadIdx.x;
    const float* src = side ? fY : fX;
    float v = src[b*DIMK + d];
    float ss = v*v;
    #pragma unroll
    for (int o = 16; o; o >>= 1) ss += __shfl_xor_sync(0xFFFFFFFFu, ss, o);
    __shared__ float ws[4];
    if ((d & 31) == 0) ws[d >> 5] = ss;
    __syncthreads();
    float tot = ws[0] + ws[1] + ws[2] + ws[3];
    float inv = 1.0f / sqrtf(tot);
    float w = v * inv;
    g_fn[side][b*DIMK + d] = w;
    float* q = out + 1 + (size_t)side * DIMK * RQ;
    q[(size_t)d * RQ + b] = w;   // new_queue[:, :B] = f.T  (4B-aligned scalar)
}

/* ------------------------------------------------------------------ */
/* 2. copy queue columns [B, R) to output — SCALAR, fully coalesced.   */
/*    Output base is out+1 (4B-aligned only), so no float4 on stores.  */
/*    Flat index space: side in {0,1}, d in [0,128), c in [B, R).      */
/* ------------------------------------------------------------------ */
__global__ void k_copyq(const float* __restrict__ qX,
                        const float* __restrict__ qY,
                        float* __restrict__ out)
{
    const size_t ncol  = (size_t)(RQ - BB);          // 130048 per row
    const size_t per_side = (size_t)DIMK * ncol;     // 16,646,144
    const size_t total = 2 * per_side;               // 33,292,288
    size_t stride = (size_t)gridDim.x * blockDim.x;
    for (size_t i = (size_t)blockIdx.x * blockDim.x + threadIdx.x;
         i < total; i += stride) {
        size_t side = i / per_side;
        size_t rem  = i - side * per_side;
        size_t d    = rem / ncol;
        size_t c    = BB + (rem - d * ncol);
        const float* q = side ? qY : qX;
        size_t off = d * RQ + c;
        out[1 + side * (size_t)DIMK * RQ + off] = q[off];
    }
}

/* ------------------------------------------------------------------ */
/* 3. phase-1 GEMM: sim[b, r] = f[b,:] . queue[:, r]                   */
/*    block tile 64x128, thread tile 8 rows x 4 cols, K=128 full       */
/* ------------------------------------------------------------------ */
__global__ void __launch_bounds__(256) k_gemm(const float* __restrict__ qX,
                                              const float* __restrict__ qY)
{
    int side = blockIdx.z;
    const float* Q = side ? qX : qY;
    const float* A = g_fn[side] + blockIdx.y * 64 * DIMK;
    float* out = g_sim + (size_t)side * BB * RQ;

    __shared__ float fs[64][DIMK];   // raw layout; compute reads are broadcast
    int tid = threadIdx.x;
    #pragma unroll
    for (int i = tid; i < 64*32; i += 256) {     // 2048 float4s
        int row = i >> 5, d4 = (i & 31) << 2;
        *(float4*)&fs[row][d4] = *(const float4*)(A + row*DIMK + d4);
    }
    __syncthreads();

    int tx = tid & 31, ty = tid >> 5;
    int c0 = blockIdx.x * 128 + tx * 4;
    int r0 = ty * 8;
    float acc[8][4];
    #pragma unroll
    for (int i = 0; i < 8; i++)
        #pragma unroll
        for (int j = 0; j < 4; j++) acc[i][j] = 0.f;

    const float* qp = Q + c0;
    #pragma unroll 2
    for (int d4 = 0; d4 < DIMK; d4 += 4) {
        float4 q0 = *(const float4*)(qp + (size_t)(d4+0) * RQ);
        float4 q1 = *(const float4*)(qp + (size_t)(d4+1) * RQ);
        float4 q2 = *(const float4*)(qp + (size_t)(d4+2) * RQ);
        float4 q3 = *(const float4*)(qp + (size_t)(d4+3) * RQ);
        #pragma unroll
        for (int i = 0; i < 8; i++) {
            float4 a = *(const float4*)&fs[r0 + i][d4];   // warp-broadcast
            acc[i][0] += a.x*q0.x; acc[i][1] += a.x*q0.y; acc[i][2] += a.x*q0.z; acc[i][3] += a.x*q0.w;
            acc[i][0] += a.y*q1.x; acc[i][1] += a.y*q1.y; acc[i][2] += a.y*q1.z; acc[i][3] += a.y*q1.w;
            acc[i][0] += a.z*q2.x; acc[i][1] += a.z*q2.y; acc[i][2] += a.z*q2.z; acc[i][3] += a.z*q2.w;
            acc[i][0] += a.w*q3.x; acc[i][1] += a.w*q3.y; acc[i][2] += a.w*q3.z; acc[i][3] += a.w*q3.w;
        }
    }

    size_t ob = (size_t)(blockIdx.y*64 + r0) * RQ + (size_t)blockIdx.x * 128 + tx * 4;
    #pragma unroll
    for (int i = 0; i < 8; i++)
        *(float4*)(out + ob + (size_t)i * RQ) =
            make_float4(acc[i][0], acc[i][1], acc[i][2], acc[i][3]);
}

/* ------------------------------------------------------------------ */
/* 4. top-10 per row over R=131072 sims                                */
/* ------------------------------------------------------------------ */
__global__ void __launch_bounds__(256) k_topk()
{
    int b = blockIdx.x, side = blockIdx.y;
    const float4* row = (const float4*)(g_sim + ((size_t)side * BB + b) * RQ);
    int tid = threadIdx.x;

    float v[NN]; int ix[NN];
    #pragma unroll
    for (int i = 0; i < NN; i++) { v[i] = -INFINITY; ix[i] = 0; }

    auto ins = [&](float s, int c) {
        if (s > v[NN-1]) {
            v[NN-1] = s; ix[NN-1] = c;
            #pragma unroll
            for (int j = NN-1; j > 0; j--) {
                if (v[j] > v[j-1]) {
                    float t = v[j]; v[j] = v[j-1]; v[j-1] = t;
                    int ti = ix[j]; ix[j] = ix[j-1]; ix[j-1] = ti;
                }
            }
        }
    };

    for (int it = 0; it < RQ/4/256; it++) {   // 128 iters
        int p = it * 256 + tid;
        float4 s = row[p];
        int c = p * 4;
        ins(s.x, c); ins(s.y, c+1); ins(s.z, c+2); ins(s.w, c+3);
    }

    /* merge 256 sorted-10 lists: 10 rounds of block argmax */
    __shared__ float    sv[256];
    __shared__ unsigned sp[256];
    __shared__ int swin;
    int ptr = 0;
    for (int k = 0; k < NN; k++) {
        bool has = ptr < NN;
        sv[tid] = has ? v[ptr] : -INFINITY;
        sp[tid] = has ? ((unsigned)ix[ptr] << 8) | (unsigned)tid : 0xFFFFFFFFu;
        __syncthreads();
        for (int s2 = 128; s2 > 0; s2 >>= 1) {
            if (tid < s2) {
                float vb = sv[tid + s2]; unsigned pb = sp[tid + s2];
                if (vb > sv[tid] || (vb == sv[tid] && pb < sp[tid])) {
                    sv[tid] = vb; sp[tid] = pb;
                }
            }
            __syncthreads();
        }
        if (tid == 0) {
            g_topk[(side*BB + b)*NN + k] = (int)(sp[0] >> 8);
            swin = (int)(sp[0] & 255u);
        }
        __syncthreads();
        if (tid == swin) ptr++;
        __syncthreads();
    }
}

/* ------------------------------------------------------------------ */
/* 5. gather neighbors transposed: nnT[d][m] = queue[d, topk[m]]       */
/* ------------------------------------------------------------------ */
__global__ void k_gather(const float* __restrict__ qX,
                         const float* __restrict__ qY)
{
    int side = blockIdx.z;
    int d    = blockIdx.y;
    int m    = blockIdx.x * blockDim.x + threadIdx.x;
    const float* Q = side ? qX : qY;
    int idx = g_topk[side*NM + m];
    g_nnT[side][(size_t)d * NM + m] = Q[(size_t)d * RQ + idx];
}

/* ------------------------------------------------------------------ */
/* 6. phase-2: fused GEMM + online logsumexp per row over 10240 cols   */
/*    block: 16 rows, thread tile 4 rows x 4 cols                      */
/* ------------------------------------------------------------------ */
__global__ void __launch_bounds__(256) k_lse()
{
    int side = blockIdx.y;
    int rb   = blockIdx.x * 16;
    __shared__ float fs[16][DIMK];
    int tid = threadIdx.x;
    const float* A = g_fn[side] + rb * DIMK;
    #pragma unroll
    for (int i = tid; i < 16*32; i += 256) {
        int row = i >> 5, d4 = (i & 31) << 2;
        *(float4*)&fs[row][d4] = *(const float4*)(A + row*DIMK + d4);
    }
    __syncthreads();

    int tx = tid & 63, ty = tid >> 6;
    int r0 = ty * 4;
    const float* nn = g_nnT[side];

    float mx[4], sm[4];
    #pragma unroll
    for (int i = 0; i < 4; i++) { mx[i] = -INFINITY; sm[i] = 0.f; }

    for (int it = 0; it < NM/256; it++) {       // 40 iters
        int c0 = it*256 + tx*4;
        float acc[4][4];
        #pragma unroll
        for (int i = 0; i < 4; i++)
            #pragma unroll
            for (int j = 0; j < 4; j++) acc[i][j] = 0.f;

        #pragma unroll 4
        for (int d4 = 0; d4 < DIMK; d4 += 4) {
            float4 q0 = *(const float4*)(nn + (size_t)(d4+0)*NM + c0);
            float4 q1 = *(const float4*)(nn + (size_t)(d4+1)*NM + c0);
            float4 q2 = *(const float4*)(nn + (size_t)(d4+2)*NM + c0);
            float4 q3 = *(const float4*)(nn + (size_t)(d4+3)*NM + c0);
            #pragma unroll
            for (int i = 0; i < 4; i++) {
                float4 a = *(const float4*)&fs[r0 + i][d4];
                acc[i][0] += a.x*q0.x; acc[i][1] += a.x*q0.y; acc[i][2] += a.x*q0.z; acc[i][3] += a.x*q0.w;
                acc[i][0] += a.y*q1.x; acc[i][1] += a.y*q1.y; acc[i][2] += a.y*q1.z; acc[i][3] += a.y*q1.w;
                acc[i][0] += a.z*q2.x; acc[i][1] += a.z*q2.y; acc[i][2] += a.z*q2.z; acc[i][3] += a.z*q2.w;
                acc[i][0] += a.w*q3.x; acc[i][1] += a.w*q3.y; acc[i][2] += a.w*q3.z; acc[i][3] += a.w*q3.w;
            }
        }
        #pragma unroll
        for (int i = 0; i < 4; i++) {
            float l0 = acc[i][0]*INVT, l1 = acc[i][1]*INVT;
            float l2 = acc[i][2]*INVT, l3 = acc[i][3]*INVT;
            float lm = fmaxf(fmaxf(l0, l1), fmaxf(l2, l3));
            float nmx = fmaxf(mx[i], lm);
            sm[i] = sm[i]*__expf(mx[i]-nmx)
                  + __expf(l0-nmx) + __expf(l1-nmx) + __expf(l2-nmx) + __expf(l3-nmx);
            mx[i] = nmx;
        }
    }

    __shared__ float cm[16][64], cs[16][64];
    #pragma unroll
    for (int i = 0; i < 4; i++) { cm[r0+i][tx] = mx[i]; cs[r0+i][tx] = sm[i]; }
    __syncthreads();
    if (tid < 16) {
        float M = -INFINITY, S = 0.f;
        for (int j = 0; j < 64; j++) {
            float m2 = cm[tid][j], s2 = cs[tid][j];
            if (m2 > M) { S = S*__expf(M - m2) + s2; M = m2; }
            else        { S += s2*__expf(m2 - M); }
        }
        g_lse[side*BB + rb + tid] = M + logf(S);
    }
}

/* ------------------------------------------------------------------ */
/* 7. positive similarities: sum_j f[b].nn[b*10+j] / TEMP              */
/* ------------------------------------------------------------------ */
__global__ void k_pos()
{
    int b = blockIdx.x, side = blockIdx.y;
    int j = threadIdx.x >> 5, lane = threadIdx.x & 31;
    int m = b*NN + j;
    const float* f = g_fn[side] + b*DIMK;
    float s = 0.f;
    #pragma unroll
    for (int d = lane; d < DIMK; d += 32)
        s += f[d] * g_nnT[side][(size_t)d * NM + m];
    #pragma unroll
    for (int o = 16; o; o >>= 1) s += __shfl_xor_sync(0xFFFFFFFFu, s, o);
    __shared__ float pj[NN];
    if (lane == 0) pj[j] = s;
    __syncthreads();
    if (threadIdx.x == 0) {
        float t = 0.f;
        #pragma unroll
        for (int q = 0; q < NN; q++) t += pj[q];
        g_pos[side*BB + b] = t * INVT;
    }
}

/* ------------------------------------------------------------------ */
/* 8. final loss = sum_sides (1/B) * sum_i (10*lse_i - possum_i)       */
/* ------------------------------------------------------------------ */
__global__ void k_loss(float* __restrict__ out)
{
    int tid = threadIdx.x;
    float a = 0.f;
    for (int i = tid; i < 2*BB; i += 256)
        a += 10.0f * g_lse[i] - g_pos[i];
    #pragma unroll
    for (int o = 16; o; o >>= 1) a += __shfl_xor_sync(0xFFFFFFFFu, a, o);
    __shared__ float w[8];
    if ((tid & 31) == 0) w[tid >> 5] = a;
    __syncthreads();
    if (tid == 0) {
        float t = 0.f;
        #pragma unroll
        for (int i = 0; i < 8; i++) t += w[i];
        out[0] = t / (float)BB;
    }
}

/* ------------------------------------------------------------------ */
extern "C" void kernel_launch(void* const* d_in, const int* in_sizes, int n_in,
                              void* d_out, int out_size)
{
    const float* fX = (const float*)d_in[0];
    const float* fY = (const float*)d_in[1];
    const float* qX = (const float*)d_in[2];
    const float* qY = (const float*)d_in[3];
    float* out = (float*)d_out;

    k_normalize<<<dim3(BB, 2), DIMK>>>(fX, fY, out);
    k_copyq   <<<1184, 256>>>(qX, qY, out);     // ~1 wave of 4-float threads
    k_gemm    <<<dim3(RQ/128, BB/64, 2), 256>>>(qX, qY);
    k_topk    <<<dim3(BB, 2), 256>>>();
    k_gather  <<<dim3(NM/256, DIMK, 2), 256>>>(qX, qY);
    k_lse     <<<dim3(BB/16, 2), 256>>>();
    k_pos     <<<dim3(BB, 2), 320>>>();
    k_loss    <<<1, 256>>>(out);
}

// round 4
// speedup vs baseline: 5.0293x; 5.0293x over previous
#include <cuda_runtime.h>
#include <cuda_bf16.h>
#include <math.h>
#include <stdint.h>

#define DIMK 128
#define RQ   131072
#define BB   1024
#define NN   10
#define NM   (BB*NN)          /* 10240 */
#define INVT 10.0f
#define NSPL1 16              /* phase-1 R splits: 8192 cols, 64 tiles each */
#define NT1   64
#define NSPL2 10              /* phase-2 splits: 1024 cols, 8 tiles each */
#define NT2   8

#define SMEM1 98304           /* A 32K + B double buffer 2x32K */
#define SMEM2 65536           /* A 32K + B 32K */

/* ------------------------- asm helpers ---------------------------- */
__device__ __forceinline__ uint32_t smem_u32(const void* p) {
    uint32_t a;
    asm("{ .reg .u64 t; cvta.to.shared.u64 t, %1; cvt.u32.u64 %0, t; }"
        : "=r"(a) : "l"(p));
    return a;
}
#define LDSM4(r0,r1,r2,r3, a) \
    asm volatile("ldmatrix.sync.aligned.m8n8.x4.shared.b16 {%0,%1,%2,%3}, [%4];" \
        : "=r"(r0),"=r"(r1),"=r"(r2),"=r"(r3) : "r"(a))
#define LDSM4T(r0,r1,r2,r3, a) \
    asm volatile("ldmatrix.sync.aligned.m8n8.x4.trans.shared.b16 {%0,%1,%2,%3}, [%4];" \
        : "=r"(r0),"=r"(r1),"=r"(r2),"=r"(r3) : "r"(a))
#define MMA16816(c0,c1,c2,c3, a0,a1,a2,a3, b0,b1) \
    asm volatile("mma.sync.aligned.m16n8k16.row.col.f32.bf16.bf16.f32 " \
        "{%0,%1,%2,%3}, {%4,%5,%6,%7}, {%8,%9}, {%0,%1,%2,%3};" \
        : "+f"(c0),"+f"(c1),"+f"(c2),"+f"(c3) \
        : "r"(a0),"r"(a1),"r"(a2),"r"(a3),"r"(b0),"r"(b1))

#define INS(V, IX, s, c) do {                                          \
    if ((s) > V[9]) {                                                  \
        V[9] = (s); IX[9] = (c);                                       \
        _Pragma("unroll")                                              \
        for (int _j = 9; _j > 0; _j--)                                 \
            if (V[_j] > V[_j-1]) {                                     \
                float _t = V[_j]; V[_j] = V[_j-1]; V[_j-1] = _t;       \
                int _ti = IX[_j]; IX[_j] = IX[_j-1]; IX[_j-1] = _ti;   \
            }                                                          \
    } } while (0)

__device__ __forceinline__ uint4 cvt8(float4 a, float4 b) {
    __nv_bfloat162 p0 = __float22bfloat162_rn(make_float2(a.x, a.y));
    __nv_bfloat162 p1 = __float22bfloat162_rn(make_float2(a.z, a.w));
    __nv_bfloat162 p2 = __float22bfloat162_rn(make_float2(b.x, b.y));
    __nv_bfloat162 p3 = __float22bfloat162_rn(make_float2(b.z, b.w));
    uint4 u;
    u.x = *(uint32_t*)&p0; u.y = *(uint32_t*)&p1;
    u.z = *(uint32_t*)&p2; u.w = *(uint32_t*)&p3;
    return u;
}

/* -------------------------- scratch ------------------------------- */
__device__ float g_fn[2][BB*DIMK];
__device__ float g_ptv[2048*NSPL1*NN];
__device__ int   g_pti[2048*NSPL1*NN];
__device__ int   g_topk[2*NM];
__device__ __nv_bfloat16 g_nnb[2][(size_t)NM*DIMK];   /* [m][k] bf16 */
__device__ float g_S[2048*NSPL2];
__device__ float g_pos[2*BB];

/* ------------------------------------------------------------------ */
/* 1. row-normalize feats; scatter f.T into output queue[:, :B]        */
/* ------------------------------------------------------------------ */
__global__ void k_normalize(const float* __restrict__ fX,
                            const float* __restrict__ fY,
                            float* __restrict__ out)
{
    int b = blockIdx.x, side = blockIdx.y, d = threadIdx.x;
    const float* src = side ? fY : fX;
    float v = src[b*DIMK + d];
    float ss = v*v;
    #pragma unroll
    for (int o = 16; o; o >>= 1) ss += __shfl_xor_sync(0xFFFFFFFFu, ss, o);
    __shared__ float ws[4];
    if ((d & 31) == 0) ws[d >> 5] = ss;
    __syncthreads();
    float inv = rsqrtf(ws[0] + ws[1] + ws[2] + ws[3]);
    float w = v * inv;
    g_fn[side][b*DIMK + d] = w;
    float* q = out + 1 + (size_t)side * DIMK * RQ;
    q[(size_t)d * RQ + b] = w;
}

/* ------------------------------------------------------------------ */
/* 2. copy queue cols [B, R) to output (scalar, coalesced)             */
/* ------------------------------------------------------------------ */
__global__ void k_copyq(const float* __restrict__ qX,
                        const float* __restrict__ qY,
                        float* __restrict__ out)
{
    const size_t ncol = (size_t)(RQ - BB);
    const size_t per_side = (size_t)DIMK * ncol;
    const size_t total = 2 * per_side;
    size_t stride = (size_t)gridDim.x * blockDim.x;
    for (size_t i = (size_t)blockIdx.x * blockDim.x + threadIdx.x;
         i < total; i += stride) {
        size_t side = i / per_side;
        size_t rem  = i - side * per_side;
        size_t d    = rem / ncol;
        size_t c    = BB + (rem - d * ncol);
        const float* q = side ? qY : qX;
        size_t off = d * RQ + c;
        out[1 + side * (size_t)DIMK * RQ + off] = q[off];
    }
}

/* ------------------------------------------------------------------ */
/* 3. FUSED bf16 HMMA sim GEMM + per-row top-10, double-buffered B     */
/* ------------------------------------------------------------------ */
__global__ void __launch_bounds__(256)
k_simtopk(const float* __restrict__ qX, const float* __restrict__ qY)
{
    extern __shared__ __align__(16) char smem[];
    const int side = blockIdx.z, mt = blockIdx.y, rs = blockIdx.x;
    const float* Q = side ? qX : qY;
    int tid = threadIdx.x, wid = tid >> 5, lane = tid & 31;
    uint32_t sb = smem_u32(smem);
    const uint32_t sbA = sb, sbB0 = sb + 32768, sbB1 = sb + 65536;
    const int c_cta = rs * (NT1 * 128);

    /* stage A: g_fn[side] rows mt*128.. as bf16, swizzled [m][k] */
    const float* Af = g_fn[side] + (size_t)mt * 128 * DIMK;
    #pragma unroll
    for (int j = 0; j < 8; j++) {
        int idx = tid + j*256;            /* 2048 chunks of 16B */
        int m = idx >> 4, kc = idx & 15;
        const float* p = Af + m*DIMK + kc*8;
        float4 f0 = *(const float4*)p;
        float4 f1 = *(const float4*)(p + 4);
        *(uint4*)(smem + m*256 + ((kc ^ (m & 7)))*16) = cvt8(f0, f1);
    }

    uint4 rbuf[8];
    auto ldtile = [&](int t) {
        int c0 = c_cta + t*128;
        #pragma unroll
        for (int j = 0; j < 8; j++) {
            int idx = tid + j*256;
            int k = idx >> 4, nc = idx & 15;
            const float* p = Q + (size_t)k*RQ + c0 + nc*8;
            float4 f0 = *(const float4*)p;
            float4 f1 = *(const float4*)(p + 4);
            rbuf[j] = cvt8(f0, f1);
        }
    };
    auto sttile = [&](uint32_t dst) {
        #pragma unroll
        for (int j = 0; j < 8; j++) {
            int idx = tid + j*256;
            int k = idx >> 4, nc = idx & 15;
            *(uint4*)(smem + (dst - sb) + k*256 + ((nc ^ (k & 7)))*16) = rbuf[j];
        }
    };

    ldtile(0);
    __syncthreads();                       /* A staged */

    /* A fragments: 8 ksteps x 4 regs */
    uint32_t a[8][4];
    {
        int m = wid*16 + (lane & 15);
        #pragma unroll
        for (int ks = 0; ks < 8; ks++) {
            int kc = ks*2 + (lane >> 4);
            uint32_t addr = sbA + m*256 + ((kc ^ (m & 7)))*16;
            LDSM4(a[ks][0], a[ks][1], a[ks][2], a[ks][3], addr);
        }
    }

    sttile(sbB0);
    __syncthreads();                       /* B tile 0 ready */

    float v0[10], v1[10]; int x0[10], x1[10];
    #pragma unroll
    for (int i = 0; i < 10; i++) {
        v0[i] = -INFINITY; v1[i] = -INFINITY; x0[i] = 0; x1[i] = 0;
    }

    for (int t = 0; t < NT1; t++) {
        if (t + 1 < NT1) ldtile(t + 1);    /* LDG overlapped with MMA */
        uint32_t bufa = (t & 1) ? sbB1 : sbB0;
        int cbase = c_cta + t*128;
        #pragma unroll 2
        for (int nt = 0; nt < 16; nt++) {
            uint32_t b[16];
            #pragma unroll
            for (int kb = 0; kb < 4; kb++) {
                int krow = kb*32 + lane;
                uint32_t addr = bufa + krow*256 + ((nt ^ (krow & 7)))*16;
                LDSM4T(b[kb*4+0], b[kb*4+1], b[kb*4+2], b[kb*4+3], addr);
            }
            float c0 = 0.f, c1 = 0.f, c2 = 0.f, c3 = 0.f;
            #pragma unroll
            for (int ks = 0; ks < 8; ks++)
                MMA16816(c0, c1, c2, c3,
                         a[ks][0], a[ks][1], a[ks][2], a[ks][3],
                         b[ks*2], b[ks*2+1]);
            int col = cbase + nt*8 + 2*(lane & 3);
            INS(v0, x0, c0, col); INS(v0, x0, c1, col+1);
            INS(v1, x1, c2, col); INS(v1, x1, c3, col+1);
        }
        if (t + 1 < NT1) { sttile((t & 1) ? sbB0 : sbB1); __syncthreads(); }
    }

    /* quad merge: lanes (l&3)=0..3 share rows g, g+8 */
    int g = lane >> 2, q = lane & 3;
    #pragma unroll
    for (int listid = 0; listid < 2; listid++) {
        float* v = listid ? v1 : v0;
        int*  ix = listid ? x1 : x0;
        int row = (side*8 + mt)*128 + wid*16 + g + listid*8;
        #pragma unroll
        for (int k = 0; k < 10; k++) {
            float bv = v[0]; int bi = ix[0]; int bq = q;
            #pragma unroll
            for (int o = 1; o <= 2; o <<= 1) {
                float ov = __shfl_xor_sync(0xFFFFFFFFu, bv, o);
                int oi = __shfl_xor_sync(0xFFFFFFFFu, bi, o);
                int oq = __shfl_xor_sync(0xFFFFFFFFu, bq, o);
                if (ov > bv || (ov == bv && oi < bi)) { bv = ov; bi = oi; bq = oq; }
            }
            if (q == 0) {
                g_ptv[((size_t)row*NSPL1 + rs)*NN + k] = bv;
                g_pti[((size_t)row*NSPL1 + rs)*NN + k] = bi;
            }
            if (q == bq) {
                #pragma unroll
                for (int j = 0; j < 9; j++) { v[j] = v[j+1]; ix[j] = ix[j+1]; }
                v[9] = -INFINITY;
            }
        }
    }
}

/* ------------------------------------------------------------------ */
/* 4. merge NSPL1 partial top-10 lists per row (warp per row)          */
/* ------------------------------------------------------------------ */
__global__ void k_merge()
{
    int rg = blockIdx.x * 8 + (threadIdx.x >> 5);
    int lane = threadIdx.x & 31;
    float v[10]; int ix[10];
    if (lane < NSPL1) {
        const float* pv = g_ptv + ((size_t)rg*NSPL1 + lane)*NN;
        const int*   pi = g_pti + ((size_t)rg*NSPL1 + lane)*NN;
        #pragma unroll
        for (int k = 0; k < 10; k++) { v[k] = pv[k]; ix[k] = pi[k]; }
    } else {
        #pragma unroll
        for (int k = 0; k < 10; k++) { v[k] = -INFINITY; ix[k] = 0x7FFFFFFF; }
    }
    #pragma unroll
    for (int k = 0; k < 10; k++) {
        float bv = v[0]; int bi = ix[0]; int bl = lane;
        #pragma unroll
        for (int o = 1; o <= 8; o <<= 1) {
            float ov = __shfl_xor_sync(0xFFFFFFFFu, bv, o);
            int oi = __shfl_xor_sync(0xFFFFFFFFu, bi, o);
            int ol = __shfl_xor_sync(0xFFFFFFFFu, bl, o);
            if (ov > bv || (ov == bv && oi < bi)) { bv = ov; bi = oi; bl = ol; }
        }
        if (lane == 0) g_topk[rg*NN + k] = bi;
        if (lane == bl) {
            #pragma unroll
            for (int j = 0; j < 9; j++) { v[j] = v[j+1]; ix[j] = ix[j+1]; }
            v[9] = -INFINITY;
        }
    }
}

/* ------------------------------------------------------------------ */
/* 5. gather neighbors as bf16 [m][k]                                  */
/* ------------------------------------------------------------------ */
__global__ void k_gather(const float* __restrict__ qX,
                         const float* __restrict__ qY)
{
    int side = blockIdx.y;
    int m = blockIdx.x * 8 + (threadIdx.x >> 5);
    int d = (threadIdx.x & 31) * 4;
    const float* Q = side ? qX : qY;
    int idx = g_topk[side*NM + m];
    float a0 = Q[(size_t)(d+0)*RQ + idx];
    float a1 = Q[(size_t)(d+1)*RQ + idx];
    float a2 = Q[(size_t)(d+2)*RQ + idx];
    float a3 = Q[(size_t)(d+3)*RQ + idx];
    __nv_bfloat162 p0 = __float22bfloat162_rn(make_float2(a0, a1));
    __nv_bfloat162 p1 = __float22bfloat162_rn(make_float2(a2, a3));
    uint2 u; u.x = *(uint32_t*)&p0; u.y = *(uint32_t*)&p1;
    *(uint2*)(&g_nnb[side][(size_t)m*DIMK + d]) = u;
}

/* ------------------------------------------------------------------ */
/* 6. FUSED bf16 HMMA logits GEMM + sum-exp per row                    */
/* ------------------------------------------------------------------ */
__global__ void __launch_bounds__(256)
k_lse2()
{
    extern __shared__ __align__(16) char smem[];
    const int side = blockIdx.z, mt = blockIdx.y, rs = blockIdx.x;
    int tid = threadIdx.x, wid = tid >> 5, lane = tid & 31;
    uint32_t sb = smem_u32(smem);
    const uint32_t sbA = sb, sbB = sb + 32768;

    const float* Af = g_fn[side] + (size_t)mt * 128 * DIMK;
    #pragma unroll
    for (int j = 0; j < 8; j++) {
        int idx = tid + j*256;
        int m = idx >> 4, kc = idx & 15;
        const float* p = Af + m*DIMK + kc*8;
        float4 f0 = *(const float4*)p;
        float4 f1 = *(const float4*)(p + 4);
        *(uint4*)(smem + m*256 + ((kc ^ (m & 7)))*16) = cvt8(f0, f1);
    }
    __syncthreads();

    uint32_t a[8][4];
    {
        int m = wid*16 + (lane & 15);
        #pragma unroll
        for (int ks = 0; ks < 8; ks++) {
            int kc = ks*2 + (lane >> 4);
            uint32_t addr = sbA + m*256 + ((kc ^ (m & 7)))*16;
            LDSM4(a[ks][0], a[ks][1], a[ks][2], a[ks][3], addr);
        }
    }

    const __nv_bfloat16* NB = g_nnb[side];
    float S0 = 0.f, S1 = 0.f;

    for (int t = 0; t < NT2; t++) {
        __syncthreads();                   /* prev tile reads done */
        int c0 = (rs * NT2 + t) * 128;
        #pragma unroll
        for (int j = 0; j < 8; j++) {
            int idx = tid + j*256;
            int n = idx >> 4, kc = idx & 15;
            uint4 u = *(const uint4*)(NB + (size_t)(c0 + n)*DIMK + kc*8);
            *(uint4*)(smem + 32768 + n*256 + ((kc ^ (n & 7)))*16) = u;
        }
        __syncthreads();

        #pragma unroll 2
        for (int nt = 0; nt < 16; nt++) {
            uint32_t b[16];
            #pragma unroll
            for (int kb = 0; kb < 4; kb++) {
                int n = nt*8 + (lane & 7);
                int kc = kb*4 + (lane >> 3);
                uint32_t addr = sbB + n*256 + ((kc ^ (n & 7)))*16;
                LDSM4(b[kb*4+0], b[kb*4+1], b[kb*4+2], b[kb*4+3], addr);
            }
            float c0f = 0.f, c1f = 0.f, c2f = 0.f, c3f = 0.f;
            #pragma unroll
            for (int ks = 0; ks < 8; ks++)
                MMA16816(c0f, c1f, c2f, c3f,
                         a[ks][0], a[ks][1], a[ks][2], a[ks][3],
                         b[ks*2], b[ks*2+1]);
            S0 += __expf(c0f*INVT) + __expf(c1f*INVT);
            S1 += __expf(c2f*INVT) + __expf(c3f*INVT);
        }
    }

    /* quad reduce and write partials */
    #pragma unroll
    for (int o = 1; o <= 2; o <<= 1) {
        S0 += __shfl_xor_sync(0xFFFFFFFFu, S0, o);
        S1 += __shfl_xor_sync(0xFFFFFFFFu, S1, o);
    }
    int g = lane >> 2, q = lane & 3;
    if (q == 0) {
        int row = (side*8 + mt)*128 + wid*16 + g;
        g_S[(size_t)row*NSPL2 + rs]       = S0;
        g_S[(size_t)(row+8)*NSPL2 + rs]   = S1;
    }
}

/* ------------------------------------------------------------------ */
/* 7. positive logits                                                  */
/* ------------------------------------------------------------------ */
__global__ void k_pos()
{
    int b = blockIdx.x, side = blockIdx.y;
    int j = threadIdx.x >> 5, lane = threadIdx.x & 31;
    int m = b*NN + j;
    const float* f = g_fn[side] + b*DIMK;
    const __nv_bfloat16* nb = g_nnb[side] + (size_t)m * DIMK;
    float s = 0.f;
    #pragma unroll
    for (int d = lane; d < DIMK; d += 32)
        s += f[d] * __bfloat162float(nb[d]);
    #pragma unroll
    for (int o = 16; o; o >>= 1) s += __shfl_xor_sync(0xFFFFFFFFu, s, o);
    __shared__ float pj[NN];
    if (lane == 0) pj[j] = s;
    __syncthreads();
    if (threadIdx.x == 0) {
        float t = 0.f;
        #pragma unroll
        for (int qq = 0; qq < NN; qq++) t += pj[qq];
        g_pos[side*BB + b] = t * INVT;
    }
}

/* ------------------------------------------------------------------ */
/* 8. final loss                                                       */
/* ------------------------------------------------------------------ */
__global__ void k_loss(float* __restrict__ out)
{
    int tid = threadIdx.x;
    float a = 0.f;
    for (int r = tid; r < 2048; r += 256) {
        float S = 0.f;
        #pragma unroll
        for (int s = 0; s < NSPL2; s++) S += g_S[(size_t)r*NSPL2 + s];
        a += 10.0f * logf(S) - g_pos[r];
    }
    #pragma unroll
    for (int o = 16; o; o >>= 1) a += __shfl_xor_sync(0xFFFFFFFFu, a, o);
    __shared__ float w[8];
    if ((tid & 31) == 0) w[tid >> 5] = a;
    __syncthreads();
    if (tid == 0) {
        float t = 0.f;
        #pragma unroll
        for (int i = 0; i < 8; i++) t += w[i];
        out[0] = t / (float)BB;
    }
}

/* ------------------------------------------------------------------ */
extern "C" void kernel_launch(void* const* d_in, const int* in_sizes, int n_in,
                              void* d_out, int out_size)
{
    const float* fX = (const float*)d_in[0];
    const float* fY = (const float*)d_in[1];
    const float* qX = (const float*)d_in[2];
    const float* qY = (const float*)d_in[3];
    float* out = (float*)d_out;

    cudaFuncSetAttribute(k_simtopk, cudaFuncAttributeMaxDynamicSharedMemorySize, SMEM1);
    cudaFuncSetAttribute(k_lse2,    cudaFuncAttributeMaxDynamicSharedMemorySize, SMEM2);

    k_normalize<<<dim3(BB, 2), DIMK>>>(fX, fY, out);
    k_copyq   <<<1184, 256>>>(qX, qY, out);
    k_simtopk <<<dim3(NSPL1, 8, 2), 256, SMEM1>>>(qX, qY);
    k_merge   <<<256, 256>>>();
    k_gather  <<<dim3(NM/8, 2), 256>>>(qX, qY);
    k_lse2    <<<dim3(NSPL2, 8, 2), 256, SMEM2>>>();
    k_pos     <<<dim3(BB, 2), 320>>>();
    k_loss    <<<1, 256>>>(out);
}